// round 14
// baseline (speedup 1.0000x reference)
#include <cuda_runtime.h>
#include <cuda_fp16.h>
#include <math_constants.h>
#include <cstdint>

// Problem constants
#define BATCH   4
#define SEQ     2048
#define DMODEL  2048
#define NHEADS  16
#define DHEAD   128
#define QKVDIM  (3 * DMODEL)       // 6144
#define NTOK    (BATCH * SEQ)      // 8192

// ---------------------------------------------------------------------------
// Scratch (__device__ globals; no cudaMalloc allowed)
// ---------------------------------------------------------------------------
__device__ __half g_x_hi[(size_t)NTOK * DMODEL];
__device__ __half g_wqkv_hi[(size_t)QKVDIM * DMODEL];  // transposed [N,K]
__device__ __half g_wout_hi[(size_t)DMODEL * DMODEL];  // transposed [N,K]
__device__ __half g_qkv_hi[(size_t)NTOK * QKVDIM];
__device__ __half g_y_hi[(size_t)NTOK * DMODEL];

// ---------------------------------------------------------------------------
// Warp-MMA / async-copy helpers (plain PTX, compute_103-safe)
// ---------------------------------------------------------------------------
__device__ __forceinline__ uint32_t smem_u32(const void* p) {
    uint32_t a;
    asm("{ .reg .u64 t; cvta.to.shared.u64 t, %1; cvt.u32.u64 %0, t; }"
        : "=r"(a) : "l"(p));
    return a;
}

__device__ __forceinline__ void ldsm4(uint32_t r[4], uint32_t addr) {
    asm volatile("ldmatrix.sync.aligned.m8n8.x4.shared.b16 {%0,%1,%2,%3}, [%4];"
                 : "=r"(r[0]), "=r"(r[1]), "=r"(r[2]), "=r"(r[3]) : "r"(addr));
}
__device__ __forceinline__ void ldsm4t(uint32_t r[4], uint32_t addr) {
    asm volatile("ldmatrix.sync.aligned.m8n8.x4.trans.shared.b16 {%0,%1,%2,%3}, [%4];"
                 : "=r"(r[0]), "=r"(r[1]), "=r"(r[2]), "=r"(r[3]) : "r"(addr));
}

__device__ __forceinline__ void mma16816f(float c[4], const uint32_t a[4],
                                          uint32_t b0, uint32_t b1) {
    asm volatile(
        "mma.sync.aligned.m16n8k16.row.col.f32.f16.f16.f32 "
        "{%0,%1,%2,%3}, {%4,%5,%6,%7}, {%8,%9}, {%0,%1,%2,%3};"
        : "+f"(c[0]), "+f"(c[1]), "+f"(c[2]), "+f"(c[3])
        : "r"(a[0]), "r"(a[1]), "r"(a[2]), "r"(a[3]), "r"(b0), "r"(b1));
}

// pack two fp32 -> f16x2 (first arg in bits [0,16))
__device__ __forceinline__ uint32_t pack_f16x2(float lo, float hi) {
    uint32_t r;
    asm("cvt.rn.f16x2.f32 %0, %1, %2;" : "=r"(r) : "f"(hi), "f"(lo));
    return r;
}

__device__ __forceinline__ void cp16(uint32_t dst, const void* src) {
    asm volatile("cp.async.cg.shared.global [%0], [%1], 16;"
                 :: "r"(dst), "l"(src));
}
#define CP_COMMIT() asm volatile("cp.async.commit_group;" ::: "memory")
#define CP_WAIT0()  asm volatile("cp.async.wait_group 0;" ::: "memory")
#define CP_WAIT1()  asm volatile("cp.async.wait_group 1;" ::: "memory")

// ---------------------------------------------------------------------------
// Convert kernels
// ---------------------------------------------------------------------------
__global__ void cvt_kernel(const float* __restrict__ in,
                           __half* __restrict__ hi, int n4)
{
    int i = blockIdx.x * blockDim.x + threadIdx.x;
    if (i >= n4) return;
    float4 v = reinterpret_cast<const float4*>(in)[i];
    unsigned short hraw[4];
    hraw[0] = __half_as_ushort(__float2half_rn(v.x));
    hraw[1] = __half_as_ushort(__float2half_rn(v.y));
    hraw[2] = __half_as_ushort(__float2half_rn(v.z));
    hraw[3] = __half_as_ushort(__float2half_rn(v.w));
    reinterpret_cast<uint64_t*>(hi)[i] = *reinterpret_cast<uint64_t*>(hraw);
}

// W [K,N] fp32 -> Thi [N,K] fp16 (transpose + round; hi only)
__global__ void transpose_cvt_kernel(const float* __restrict__ W,
                                     __half* __restrict__ Thi,
                                     int K, int N)
{
    __shared__ float tile[32][33];
    int nx = blockIdx.x * 32 + threadIdx.x;
    int k0 = blockIdx.y * 32;
#pragma unroll
    for (int j = 0; j < 32; j += 8)
        tile[threadIdx.y + j][threadIdx.x] = W[(size_t)(k0 + threadIdx.y + j) * N + nx];
    __syncthreads();
    int k = k0 + threadIdx.x;
    int nbase = blockIdx.x * 32 + threadIdx.y;
#pragma unroll
    for (int j = 0; j < 32; j += 8)
        Thi[(size_t)(nbase + j) * K + k] = __float2half_rn(tile[threadIdx.x][threadIdx.y + j]);
}

// ---------------------------------------------------------------------------
// fp16 1-term GEMM via warp mma.sync, cp.async double buffering:
//   C[M,N] = A[M,K] @ B[N,K]^T + bias
// CTA tile 128x256, 8 warps (2 M x 4 N), warp tile 64x64, K-chunk 64.
// 1 CTA/SM, deep per-warp ILP (8 ldsm -> 32 MMA per k16 step).
// ---------------------------------------------------------------------------
#define TBM 128
#define TBN 256
#define TKC 64
#define STRB 144                 // smem row stride bytes (64 fp16 + 16 pad)
#define ATILEB (128 * STRB)      // 18432 (A: 128 rows)
#define BTILEB (256 * STRB)      // 36864 (B: 256 rows)
#define STAGEB (ATILEB + BTILEB) // 55296
#define GSMEM (2 * STAGEB)       // 110592

__global__ __launch_bounds__(256, 1)
void gemm_mma_kernel(const __half* __restrict__ Ahi,
                     const __half* __restrict__ Bhi,
                     const float* __restrict__ bias,
                     float* __restrict__ Cf,
                     __half* __restrict__ Chi,
                     int M, int N, int K)
{
    extern __shared__ char sm[];
    const uint32_t sbase = smem_u32(sm);
    const int tid = threadIdx.x;
    const int wid = tid >> 5;
    const int lane = tid & 31;
    const int m0 = blockIdx.y * TBM;
    const int n0 = blockIdx.x * TBN;
    const int wm = wid & 1;          // 2 warps in M (64 rows each)
    const int wn = wid >> 1;         // 4 warps in N (64 cols each)

    const int lc16 = tid & 7;

    float acc[4][8][4];
#pragma unroll
    for (int i = 0; i < 4; ++i)
#pragma unroll
        for (int j = 0; j < 8; ++j)
#pragma unroll
            for (int k = 0; k < 4; ++k) acc[i][j][k] = 0.f;

    const int arow = lane & 15;
    const int akb  = (lane & 16) ? 16 : 0;
    const int brow = ((lane & 16) ? 8 : 0) + (lane & 7);
    const int bkb  = (lane & 8) ? 16 : 0;

    const uint32_t aL = sbase + (wm * 64 + arow) * STRB + akb;
    const uint32_t bL = sbase + ATILEB + (wn * 64 + brow) * STRB + bkb;

    const int nchunk = K / TKC;

#define GEMM_ISSUE(CHUNK, STAGE)                                              \
    {                                                                         \
        const int k0_ = (CHUNK) * TKC;                                        \
        const uint32_t sb_ = sbase + (STAGE) * STAGEB;                        \
        _Pragma("unroll")                                                     \
        for (int l = 0; l < 4; ++l) {                                         \
            int row = (tid + l * 256) >> 3;                                   \
            uint32_t so = row * STRB + lc16 * 16;                             \
            size_t ga = (size_t)(m0 + row) * K + k0_ + lc16 * 8;              \
            cp16(sb_ + so, Ahi + ga);                                         \
        }                                                                     \
        _Pragma("unroll")                                                     \
        for (int l = 0; l < 8; ++l) {                                         \
            int row = (tid + l * 256) >> 3;                                   \
            uint32_t so = row * STRB + lc16 * 16;                             \
            size_t gb = (size_t)(n0 + row) * K + k0_ + lc16 * 8;              \
            cp16(sb_ + ATILEB + so, Bhi + gb);                                \
        }                                                                     \
    }

    GEMM_ISSUE(0, 0);
    CP_COMMIT();

    for (int c = 0; c < nchunk; ++c) {
        if (c + 1 < nchunk) {
            GEMM_ISSUE(c + 1, (c + 1) & 1);
            CP_COMMIT();
            CP_WAIT1();
        } else {
            CP_WAIT0();
        }
        __syncthreads();

        const uint32_t stoff = (uint32_t)(c & 1) * STAGEB;
#pragma unroll
        for (int ks = 0; ks < 4; ++ks) {
            uint32_t ah[4][4], bh[4][4];
#pragma unroll
            for (int mt = 0; mt < 4; ++mt)
                ldsm4(ah[mt], aL + stoff + mt * (16 * STRB) + ks * 32);
#pragma unroll
            for (int np = 0; np < 4; ++np)
                ldsm4(bh[np], bL + stoff + np * (16 * STRB) + ks * 32);
#pragma unroll
            for (int mt = 0; mt < 4; ++mt)
#pragma unroll
                for (int nt = 0; nt < 8; ++nt)
                    mma16816f(acc[mt][nt], ah[mt],
                              bh[nt >> 1][(nt & 1) * 2], bh[nt >> 1][(nt & 1) * 2 + 1]);
        }
        __syncthreads();
    }
#undef GEMM_ISSUE

    // Epilogue
    const int rbase = m0 + wm * 64 + (lane >> 2);
    const int cbase = n0 + wn * 64 + (lane & 3) * 2;
    if (Cf) {
#pragma unroll
        for (int mt = 0; mt < 4; ++mt) {
#pragma unroll
            for (int nt = 0; nt < 8; ++nt) {
                int r = rbase + mt * 16;
                int col = cbase + nt * 8;
                float2 bv = *reinterpret_cast<const float2*>(bias + col);
                float2 v0, v1;
                v0.x = acc[mt][nt][0] + bv.x;
                v0.y = acc[mt][nt][1] + bv.y;
                v1.x = acc[mt][nt][2] + bv.x;
                v1.y = acc[mt][nt][3] + bv.y;
                *reinterpret_cast<float2*>(Cf + (size_t)r * N + col) = v0;
                *reinterpret_cast<float2*>(Cf + (size_t)(r + 8) * N + col) = v1;
            }
        }
    } else {
        // hi-only fp16 epilogue
#pragma unroll
        for (int mt = 0; mt < 4; ++mt) {
#pragma unroll
            for (int nt = 0; nt < 8; ++nt) {
                int r = rbase + mt * 16;
                int col = cbase + nt * 8;
                float2 bv = *reinterpret_cast<const float2*>(bias + col);
                uint32_t hp0 = pack_f16x2(acc[mt][nt][0] + bv.x,
                                          acc[mt][nt][1] + bv.y);
                uint32_t hp1 = pack_f16x2(acc[mt][nt][2] + bv.x,
                                          acc[mt][nt][3] + bv.y);
                *reinterpret_cast<uint32_t*>(Chi + (size_t)r * N + col) = hp0;
                *reinterpret_cast<uint32_t*>(Chi + (size_t)(r + 8) * N + col) = hp1;
            }
        }
    }
}

// ---------------------------------------------------------------------------
// Tensor-core flash attention (pure fp16 inputs, fp32 accum), causal,
// muP scale 1/DHEAD, cp.async double-buffered K/V pipeline. (unchanged R13)
// ---------------------------------------------------------------------------
#define ASTR 272                 // smem row stride bytes (128 fp16 + 16 pad)
#define ATILE (64 * ASTR)        // 17408 bytes per tile
#define FSM_Q  0
#define FSM_K0 (1 * ATILE)
#define FSM_K1 (2 * ATILE)
#define FSM_V0 (3 * ATILE)
#define FSM_V1 (4 * ATILE)
#define FSMEM  (5 * ATILE)       // 87040

__global__ __launch_bounds__(128, 2)
void flash_mma_kernel(const __half* __restrict__ qkvh,
                      __half* __restrict__ yh)
{
    extern __shared__ char sm[];
    const uint32_t sbase = smem_u32(sm);
    const int tid = threadIdx.x;
    const int w = tid >> 5;
    const int lane = tid & 31;

    const int qtile = blockIdx.x;
    const int bh = blockIdx.y;
    const int b = bh >> 4;
    const int h = bh & 15;
    const int q0 = qtile * 64;

#pragma unroll
    for (int l = 0; l < 8; ++l) {
        int f = tid + l * 128;
        int row = f >> 4;
        int c8 = f & 15;
        size_t g = (size_t)(b * SEQ + q0 + row) * QKVDIM + h * DHEAD + c8 * 8;
        uint32_t so = row * ASTR + c8 * 16;
        *reinterpret_cast<uint4*>(sm + FSM_Q + so) =
            *reinterpret_cast<const uint4*>(qkvh + g);
    }

    float o[16][4];
#pragma unroll
    for (int i = 0; i < 16; ++i)
#pragma unroll
        for (int j = 0; j < 4; ++j) o[i][j] = 0.f;
    float mrow[2] = {-CUDART_INF_F, -CUDART_INF_F};
    float lrow[2] = {0.f, 0.f};

    const uint32_t qLane = sbase + FSM_Q + (w * 16 + (lane & 15)) * ASTR +
                           ((lane & 16) ? 16 : 0);
    const uint32_t kLane0 = sbase + FSM_K0 +
                            (((lane & 16) ? 8 : 0) + (lane & 7)) * ASTR +
                            ((lane & 8) ? 16 : 0);
    const uint32_t vLane0 = sbase + FSM_V0 + (lane & 15) * ASTR +
                            ((lane & 16) ? 16 : 0);

    const float SCALE_LOG2E = (1.0f / (float)DHEAD) * 1.44269504088896f;

    const int kvc8 = tid & 15;

#define FLASH_ISSUE(KT, STAGE)                                                \
    {                                                                         \
        const int k0_ = (KT) * 64;                                            \
        const uint32_t koff = sbase + FSM_K0 + (STAGE) * ATILE;               \
        const uint32_t voff = sbase + FSM_V0 + (STAGE) * ATILE;               \
        _Pragma("unroll")                                                     \
        for (int l = 0; l < 8; ++l) {                                         \
            int row = (tid + l * 128) >> 4;                                   \
            size_t g = (size_t)(b * SEQ + k0_ + row) * QKVDIM +               \
                       h * DHEAD + kvc8 * 8;                                  \
            uint32_t so = row * ASTR + kvc8 * 16;                             \
            cp16(koff + so, qkvh + DMODEL + g);                               \
            cp16(voff + so, qkvh + 2 * DMODEL + g);                           \
        }                                                                     \
    }

    FLASH_ISSUE(0, 0);
    CP_COMMIT();

    for (int kt = 0; kt <= qtile; ++kt) {
        __syncthreads();
        if (kt + 1 <= qtile) {
            FLASH_ISSUE(kt + 1, (kt + 1) & 1);
            CP_COMMIT();
            CP_WAIT1();
        } else {
            CP_WAIT0();
        }
        __syncthreads();

        const uint32_t stg = (uint32_t)(kt & 1) * ATILE;
        const uint32_t kLane = kLane0 + stg;
        const uint32_t vLane = vLane0 + stg;

        float sacc[8][4];
#pragma unroll
        for (int i = 0; i < 8; ++i)
#pragma unroll
            for (int j = 0; j < 4; ++j) sacc[i][j] = 0.f;

#pragma unroll
        for (int ks = 0; ks < 8; ++ks) {
            uint32_t ah[4];
            ldsm4(ah, qLane + ks * 32);
#pragma unroll
            for (int g = 0; g < 4; ++g) {
                uint32_t bhf[4];
                ldsm4(bhf, kLane + g * (16 * ASTR) + ks * 32);
                mma16816f(sacc[2 * g],     ah, bhf[0], bhf[1]);
                mma16816f(sacc[2 * g + 1], ah, bhf[2], bhf[3]);
            }
        }

        if (kt == qtile) {
            const int rA = w * 16 + (lane >> 2);
#pragma unroll
            for (int nt = 0; nt < 8; ++nt) {
#pragma unroll
                for (int e = 0; e < 4; ++e) {
                    int col = nt * 8 + (lane & 3) * 2 + (e & 1);
                    int row = rA + ((e & 2) ? 8 : 0);
                    if (col > row) sacc[nt][e] = -CUDART_INF_F;
                }
            }
        }

        float mx0 = -CUDART_INF_F, mx1 = -CUDART_INF_F;
#pragma unroll
        for (int nt = 0; nt < 8; ++nt) {
            mx0 = fmaxf(mx0, fmaxf(sacc[nt][0], sacc[nt][1]));
            mx1 = fmaxf(mx1, fmaxf(sacc[nt][2], sacc[nt][3]));
        }
        mx0 = fmaxf(mx0, __shfl_xor_sync(0xffffffffu, mx0, 1));
        mx0 = fmaxf(mx0, __shfl_xor_sync(0xffffffffu, mx0, 2));
        mx1 = fmaxf(mx1, __shfl_xor_sync(0xffffffffu, mx1, 1));
        mx1 = fmaxf(mx1, __shfl_xor_sync(0xffffffffu, mx1, 2));
        float mn0 = fmaxf(mrow[0], mx0 * SCALE_LOG2E);
        float mn1 = fmaxf(mrow[1], mx1 * SCALE_LOG2E);
        float alpha0 = exp2f(mrow[0] - mn0);
        float alpha1 = exp2f(mrow[1] - mn1);
        mrow[0] = mn0; mrow[1] = mn1;

        float sum0 = 0.f, sum1 = 0.f;
#pragma unroll
        for (int nt = 0; nt < 8; ++nt) {
            float p0 = exp2f(sacc[nt][0] * SCALE_LOG2E - mn0);
            float p1 = exp2f(sacc[nt][1] * SCALE_LOG2E - mn0);
            float p2 = exp2f(sacc[nt][2] * SCALE_LOG2E - mn1);
            float p3 = exp2f(sacc[nt][3] * SCALE_LOG2E - mn1);
            sacc[nt][0] = p0; sacc[nt][1] = p1;
            sacc[nt][2] = p2; sacc[nt][3] = p3;
            sum0 += p0 + p1;
            sum1 += p2 + p3;
        }
        sum0 += __shfl_xor_sync(0xffffffffu, sum0, 1);
        sum0 += __shfl_xor_sync(0xffffffffu, sum0, 2);
        sum1 += __shfl_xor_sync(0xffffffffu, sum1, 1);
        sum1 += __shfl_xor_sync(0xffffffffu, sum1, 2);
        lrow[0] = alpha0 * lrow[0] + sum0;
        lrow[1] = alpha1 * lrow[1] + sum1;

#pragma unroll
        for (int nt = 0; nt < 16; ++nt) {
            o[nt][0] *= alpha0; o[nt][1] *= alpha0;
            o[nt][2] *= alpha1; o[nt][3] *= alpha1;
        }

#pragma unroll
        for (int kc = 0; kc < 4; ++kc) {
            uint32_t pa_h[4];
#pragma unroll
            for (int half = 0; half < 2; ++half) {
                const float* s2 = sacc[2 * kc + half];
#pragma unroll
                for (int rr = 0; rr < 2; ++rr) {
                    pa_h[half * 2 + rr] = pack_f16x2(s2[rr * 2 + 0], s2[rr * 2 + 1]);
                }
            }
#pragma unroll
            for (int ng = 0; ng < 8; ++ng) {
                uint32_t vh[4];
                ldsm4t(vh, vLane + kc * (16 * ASTR) + ng * 32);
                mma16816f(o[2 * ng],     pa_h, vh[0], vh[1]);
                mma16816f(o[2 * ng + 1], pa_h, vh[2], vh[3]);
            }
        }
    }
#undef FLASH_ISSUE

    const float inv0 = 1.0f / lrow[0];
    const float inv1 = 1.0f / lrow[1];
    const int rowA = q0 + w * 16 + (lane >> 2);
#pragma unroll
    for (int nt = 0; nt < 16; ++nt) {
        int col = h * DHEAD + nt * 8 + (lane & 3) * 2;
        uint32_t hp0 = pack_f16x2(o[nt][0] * inv0, o[nt][1] * inv0);
        uint32_t hp1 = pack_f16x2(o[nt][2] * inv1, o[nt][3] * inv1);
        size_t r0 = (size_t)(b * SEQ + rowA) * DMODEL + col;
        size_t r1 = (size_t)(b * SEQ + rowA + 8) * DMODEL + col;
        *reinterpret_cast<uint32_t*>(yh + r0) = hp0;
        *reinterpret_cast<uint32_t*>(yh + r1) = hp1;
    }
}

// ---------------------------------------------------------------------------
// Launch
// ---------------------------------------------------------------------------
extern "C" void kernel_launch(void* const* d_in, const int* in_sizes, int n_in,
                              void* d_out, int out_size)
{
    const float* x     = (const float*)d_in[0];
    const float* W_qkv = (const float*)d_in[1];
    const float* b_qkv = (const float*)d_in[2];
    const float* W_out = (const float*)d_in[3];
    const float* b_out = (const float*)d_in[4];
    float* out = (float*)d_out;

    void *p_xh, *p_wqh, *p_woh, *p_qh, *p_yh;
    cudaGetSymbolAddress(&p_xh, g_x_hi);
    cudaGetSymbolAddress(&p_wqh, g_wqkv_hi);
    cudaGetSymbolAddress(&p_woh, g_wout_hi);
    cudaGetSymbolAddress(&p_qh, g_qkv_hi);
    cudaGetSymbolAddress(&p_yh, g_y_hi);

    cudaFuncSetAttribute(gemm_mma_kernel,
                         cudaFuncAttributeMaxDynamicSharedMemorySize, GSMEM);
    cudaFuncSetAttribute(flash_mma_kernel,
                         cudaFuncAttributeMaxDynamicSharedMemorySize, FSMEM);

    // 0) Converts
    {
        int n4 = NTOK * DMODEL / 4;
        cvt_kernel<<<(n4 + 255) / 256, 256>>>(x, (__half*)p_xh, n4);
        dim3 blk(32, 8);
        transpose_cvt_kernel<<<dim3(QKVDIM / 32, DMODEL / 32), blk>>>(
            W_qkv, (__half*)p_wqh, DMODEL, QKVDIM);
        transpose_cvt_kernel<<<dim3(DMODEL / 32, DMODEL / 32), blk>>>(
            W_out, (__half*)p_woh, DMODEL, DMODEL);
    }

    // 1) QKV projection (pure fp16) -> qkv hi fp16
    gemm_mma_kernel<<<dim3(QKVDIM / TBN, NTOK / TBM), 256, GSMEM>>>(
        (const __half*)p_xh, (const __half*)p_wqh,
        b_qkv, nullptr, (__half*)p_qh,
        NTOK, QKVDIM, DMODEL);

    // 2) Attention (pure fp16 flash, cp.async pipelined) -> y hi fp16
    flash_mma_kernel<<<dim3(SEQ / 64, BATCH * NHEADS), 128, FSMEM>>>(
        (const __half*)p_qh, (__half*)p_yh);

    // 3) Output projection (pure fp16) -> fp32 out
    gemm_mma_kernel<<<dim3(DMODEL / TBN, NTOK / TBM), 256, GSMEM>>>(
        (const __half*)p_yh, (const __half*)p_woh,
        b_out, out, nullptr,
        NTOK, DMODEL, DMODEL);
}

// round 16
// speedup vs baseline: 1.1260x; 1.1260x over previous
#include <cuda_runtime.h>
#include <cuda_fp16.h>
#include <math_constants.h>
#include <cstdint>

// Problem constants
#define BATCH   4
#define SEQ     2048
#define DMODEL  2048
#define NHEADS  16
#define DHEAD   128
#define QKVDIM  (3 * DMODEL)       // 6144
#define NTOK    (BATCH * SEQ)      // 8192

// ---------------------------------------------------------------------------
// Scratch (__device__ globals; no cudaMalloc allowed)
// ---------------------------------------------------------------------------
__device__ __half g_x_hi[(size_t)NTOK * DMODEL];
__device__ __half g_wqkv_hi[(size_t)QKVDIM * DMODEL];  // transposed [N,K]
__device__ __half g_wout_hi[(size_t)DMODEL * DMODEL];  // transposed [N,K]
__device__ __half g_qkv_hi[(size_t)NTOK * QKVDIM];
__device__ __half g_y_hi[(size_t)NTOK * DMODEL];

// ---------------------------------------------------------------------------
// Warp-MMA / async-copy helpers (plain PTX, compute_103-safe)
// ---------------------------------------------------------------------------
__device__ __forceinline__ uint32_t smem_u32(const void* p) {
    uint32_t a;
    asm("{ .reg .u64 t; cvta.to.shared.u64 t, %1; cvt.u32.u64 %0, t; }"
        : "=r"(a) : "l"(p));
    return a;
}

__device__ __forceinline__ void ldsm4(uint32_t r[4], uint32_t addr) {
    asm volatile("ldmatrix.sync.aligned.m8n8.x4.shared.b16 {%0,%1,%2,%3}, [%4];"
                 : "=r"(r[0]), "=r"(r[1]), "=r"(r[2]), "=r"(r[3]) : "r"(addr));
}
__device__ __forceinline__ void ldsm4t(uint32_t r[4], uint32_t addr) {
    asm volatile("ldmatrix.sync.aligned.m8n8.x4.trans.shared.b16 {%0,%1,%2,%3}, [%4];"
                 : "=r"(r[0]), "=r"(r[1]), "=r"(r[2]), "=r"(r[3]) : "r"(addr));
}

__device__ __forceinline__ void mma16816f(float c[4], const uint32_t a[4],
                                          uint32_t b0, uint32_t b1) {
    asm volatile(
        "mma.sync.aligned.m16n8k16.row.col.f32.f16.f16.f32 "
        "{%0,%1,%2,%3}, {%4,%5,%6,%7}, {%8,%9}, {%0,%1,%2,%3};"
        : "+f"(c[0]), "+f"(c[1]), "+f"(c[2]), "+f"(c[3])
        : "r"(a[0]), "r"(a[1]), "r"(a[2]), "r"(a[3]), "r"(b0), "r"(b1));
}

// pack two fp32 -> f16x2 (first arg in bits [0,16))
__device__ __forceinline__ uint32_t pack_f16x2(float lo, float hi) {
    uint32_t r;
    asm("cvt.rn.f16x2.f32 %0, %1, %2;" : "=r"(r) : "f"(hi), "f"(lo));
    return r;
}

__device__ __forceinline__ void cp16(uint32_t dst, const void* src) {
    asm volatile("cp.async.cg.shared.global [%0], [%1], 16;"
                 :: "r"(dst), "l"(src));
}
#define CP_COMMIT() asm volatile("cp.async.commit_group;" ::: "memory")
#define CP_WAIT0()  asm volatile("cp.async.wait_group 0;" ::: "memory")
#define CP_WAIT1()  asm volatile("cp.async.wait_group 1;" ::: "memory")

// ---------------------------------------------------------------------------
// Convert kernels
// ---------------------------------------------------------------------------
__global__ void cvt_kernel(const float* __restrict__ in,
                           __half* __restrict__ hi, int n4)
{
    int i = blockIdx.x * blockDim.x + threadIdx.x;
    if (i >= n4) return;
    float4 v = reinterpret_cast<const float4*>(in)[i];
    unsigned short hraw[4];
    hraw[0] = __half_as_ushort(__float2half_rn(v.x));
    hraw[1] = __half_as_ushort(__float2half_rn(v.y));
    hraw[2] = __half_as_ushort(__float2half_rn(v.z));
    hraw[3] = __half_as_ushort(__float2half_rn(v.w));
    reinterpret_cast<uint64_t*>(hi)[i] = *reinterpret_cast<uint64_t*>(hraw);
}

// W [K,N] fp32 -> Thi [N,K] fp16 (transpose + round; hi only)
__global__ void transpose_cvt_kernel(const float* __restrict__ W,
                                     __half* __restrict__ Thi,
                                     int K, int N)
{
    __shared__ float tile[32][33];
    int nx = blockIdx.x * 32 + threadIdx.x;
    int k0 = blockIdx.y * 32;
#pragma unroll
    for (int j = 0; j < 32; j += 8)
        tile[threadIdx.y + j][threadIdx.x] = W[(size_t)(k0 + threadIdx.y + j) * N + nx];
    __syncthreads();
    int k = k0 + threadIdx.x;
    int nbase = blockIdx.x * 32 + threadIdx.y;
#pragma unroll
    for (int j = 0; j < 32; j += 8)
        Thi[(size_t)(nbase + j) * K + k] = __float2half_rn(tile[threadIdx.x][threadIdx.y + j]);
}

// ---------------------------------------------------------------------------
// fp16 GEMM via warp mma.sync, cp.async double buffering (R13 config):
//   C[M,N] = A[M,K] @ B[N,K]^T + bias
// CTA tile 128x128, 8 warps (2 M x 4 N), warp tile 64x32, K-chunk 64, 2 CTA/SM.
// ---------------------------------------------------------------------------
#define TBM 128
#define TBN 128
#define TKC 64
#define STRB 144                 // smem row stride bytes (64 fp16 + 16 pad)
#define TILEB (128 * STRB)       // 18432
#define STAGEB (2 * TILEB)       // 36864: [A][B]
#define GSMEM (2 * STAGEB)       // 73728

__global__ __launch_bounds__(256, 2)
void gemm_mma_kernel(const __half* __restrict__ Ahi,
                     const __half* __restrict__ Bhi,
                     const float* __restrict__ bias,
                     float* __restrict__ Cf,
                     __half* __restrict__ Chi,
                     int M, int N, int K)
{
    extern __shared__ char sm[];
    const uint32_t sbase = smem_u32(sm);
    const int tid = threadIdx.x;
    const int wid = tid >> 5;
    const int lane = tid & 31;
    const int m0 = blockIdx.y * TBM;
    const int n0 = blockIdx.x * TBN;
    const int wm = wid & 1;
    const int wn = wid >> 1;

    const int lc16 = tid & 7;

    float acc[4][4][4];
#pragma unroll
    for (int i = 0; i < 4; ++i)
#pragma unroll
        for (int j = 0; j < 4; ++j)
#pragma unroll
            for (int k = 0; k < 4; ++k) acc[i][j][k] = 0.f;

    const int arow = lane & 15;
    const int akb  = (lane & 16) ? 16 : 0;
    const int brow = ((lane & 16) ? 8 : 0) + (lane & 7);
    const int bkb  = (lane & 8) ? 16 : 0;

    const uint32_t aL = sbase + (wm * 64 + arow) * STRB + akb;
    const uint32_t bL = sbase + TILEB + (wn * 32 + brow) * STRB + bkb;

    const int nchunk = K / TKC;

#define GEMM_ISSUE(CHUNK, STAGE)                                              \
    {                                                                         \
        const int k0_ = (CHUNK) * TKC;                                        \
        const uint32_t sb_ = sbase + (STAGE) * STAGEB;                        \
        _Pragma("unroll")                                                     \
        for (int l = 0; l < 4; ++l) {                                         \
            int row = (tid + l * 256) >> 3;                                   \
            uint32_t so = row * STRB + lc16 * 16;                             \
            size_t ga = (size_t)(m0 + row) * K + k0_ + lc16 * 8;              \
            size_t gb = (size_t)(n0 + row) * K + k0_ + lc16 * 8;              \
            cp16(sb_ + so, Ahi + ga);                                         \
            cp16(sb_ + TILEB + so, Bhi + gb);                                 \
        }                                                                     \
    }

    GEMM_ISSUE(0, 0);
    CP_COMMIT();

    for (int c = 0; c < nchunk; ++c) {
        if (c + 1 < nchunk) {
            GEMM_ISSUE(c + 1, (c + 1) & 1);
            CP_COMMIT();
            CP_WAIT1();
        } else {
            CP_WAIT0();
        }
        __syncthreads();

        const uint32_t stoff = (uint32_t)(c & 1) * STAGEB;
#pragma unroll
        for (int ks = 0; ks < 4; ++ks) {
            uint32_t ah[4][4], bh[2][4];
#pragma unroll
            for (int mt = 0; mt < 4; ++mt)
                ldsm4(ah[mt], aL + stoff + mt * (16 * STRB) + ks * 32);
#pragma unroll
            for (int np = 0; np < 2; ++np)
                ldsm4(bh[np], bL + stoff + np * (16 * STRB) + ks * 32);
#pragma unroll
            for (int mt = 0; mt < 4; ++mt)
#pragma unroll
                for (int nt = 0; nt < 4; ++nt)
                    mma16816f(acc[mt][nt], ah[mt],
                              bh[nt >> 1][(nt & 1) * 2], bh[nt >> 1][(nt & 1) * 2 + 1]);
        }
        __syncthreads();
    }
#undef GEMM_ISSUE

    // Epilogue
    const int rbase = m0 + wm * 64 + (lane >> 2);
    const int cbase = n0 + wn * 32 + (lane & 3) * 2;
    if (Cf) {
#pragma unroll
        for (int mt = 0; mt < 4; ++mt) {
#pragma unroll
            for (int nt = 0; nt < 4; ++nt) {
                int r = rbase + mt * 16;
                int col = cbase + nt * 8;
                float2 bv = *reinterpret_cast<const float2*>(bias + col);
                float2 v0, v1;
                v0.x = acc[mt][nt][0] + bv.x;
                v0.y = acc[mt][nt][1] + bv.y;
                v1.x = acc[mt][nt][2] + bv.x;
                v1.y = acc[mt][nt][3] + bv.y;
                *reinterpret_cast<float2*>(Cf + (size_t)r * N + col) = v0;
                *reinterpret_cast<float2*>(Cf + (size_t)(r + 8) * N + col) = v1;
            }
        }
    } else {
#pragma unroll
        for (int mt = 0; mt < 4; ++mt) {
#pragma unroll
            for (int nt = 0; nt < 4; ++nt) {
                int r = rbase + mt * 16;
                int col = cbase + nt * 8;
                float2 bv = *reinterpret_cast<const float2*>(bias + col);
                uint32_t hp0 = pack_f16x2(acc[mt][nt][0] + bv.x,
                                          acc[mt][nt][1] + bv.y);
                uint32_t hp1 = pack_f16x2(acc[mt][nt][2] + bv.x,
                                          acc[mt][nt][3] + bv.y);
                *reinterpret_cast<uint32_t*>(Chi + (size_t)r * N + col) = hp0;
                *reinterpret_cast<uint32_t*>(Chi + (size_t)(r + 8) * N + col) = hp1;
            }
        }
    }
}

// ---------------------------------------------------------------------------
// Tensor-core flash attention (pure fp16, fp32 accum), causal, muP 1/DHEAD.
// BM=128 (8 warps x 16 query rows), BN=64, D=128; cp.async double-buffered KV.
// Halves KV global/L2 traffic vs BM=64. Reads qkv hi fp16; writes y hi fp16.
// ---------------------------------------------------------------------------
#define ASTR 272                  // smem row stride bytes (128 fp16 + 16 pad)
#define QTILEB (128 * ASTR)       // 34816 (Q: 128 rows)
#define KVTILE (64 * ASTR)        // 17408 (K/V: 64 rows)
#define FSM_Q  0
#define FSM_K0 (QTILEB)
#define FSM_K1 (QTILEB + 1 * KVTILE)
#define FSM_V0 (QTILEB + 2 * KVTILE)
#define FSM_V1 (QTILEB + 3 * KVTILE)
#define FSMEM  (QTILEB + 4 * KVTILE)   // 104448

__global__ __launch_bounds__(256, 2)
void flash_mma_kernel(const __half* __restrict__ qkvh,
                      __half* __restrict__ yh)
{
    extern __shared__ char sm[];
    const uint32_t sbase = smem_u32(sm);
    const int tid = threadIdx.x;
    const int w = tid >> 5;          // 0..7, warp owns rows w*16..w*16+15
    const int lane = tid & 31;

    const int qtile = blockIdx.x;    // 0..15
    const int bh = blockIdx.y;       // 0..63
    const int b = bh >> 4;
    const int h = bh & 15;
    const int q0 = qtile * 128;

    // Q load: 128 rows x 16 lines = 2048 lines; 256 threads x 8
#pragma unroll
    for (int l = 0; l < 8; ++l) {
        int f = tid + l * 256;
        int row = f >> 4;
        int c8 = f & 15;
        size_t g = (size_t)(b * SEQ + q0 + row) * QKVDIM + h * DHEAD + c8 * 8;
        uint32_t so = row * ASTR + c8 * 16;
        *reinterpret_cast<uint4*>(sm + FSM_Q + so) =
            *reinterpret_cast<const uint4*>(qkvh + g);
    }

    float o[16][4];
#pragma unroll
    for (int i = 0; i < 16; ++i)
#pragma unroll
        for (int j = 0; j < 4; ++j) o[i][j] = 0.f;
    float mrow[2] = {-CUDART_INF_F, -CUDART_INF_F};
    float lrow[2] = {0.f, 0.f};

    const uint32_t qLane = sbase + FSM_Q + (w * 16 + (lane & 15)) * ASTR +
                           ((lane & 16) ? 16 : 0);
    const uint32_t kLane0 = sbase + FSM_K0 +
                            (((lane & 16) ? 8 : 0) + (lane & 7)) * ASTR +
                            ((lane & 8) ? 16 : 0);
    const uint32_t vLane0 = sbase + FSM_V0 + (lane & 15) * ASTR +
                            ((lane & 16) ? 16 : 0);

    const float SCALE_LOG2E = (1.0f / (float)DHEAD) * 1.44269504088896f;

    // KV load: 64 rows x 16 lines = 1024 lines; 256 threads x 4
    const int kvc8 = tid & 15;

#define FLASH_ISSUE(KT, STAGE)                                                \
    {                                                                         \
        const int k0_ = (KT) * 64;                                            \
        const uint32_t koff = sbase + FSM_K0 + (STAGE) * KVTILE;              \
        const uint32_t voff = sbase + FSM_V0 + (STAGE) * KVTILE;              \
        _Pragma("unroll")                                                     \
        for (int l = 0; l < 4; ++l) {                                         \
            int row = (tid + l * 256) >> 4;                                   \
            size_t g = (size_t)(b * SEQ + k0_ + row) * QKVDIM +               \
                       h * DHEAD + kvc8 * 8;                                  \
            uint32_t so = row * ASTR + kvc8 * 16;                             \
            cp16(koff + so, qkvh + DMODEL + g);                               \
            cp16(voff + so, qkvh + 2 * DMODEL + g);                           \
        }                                                                     \
    }

    const int ktmax = 2 * qtile + 1;   // K tiles cover [0, q0+128)

    FLASH_ISSUE(0, 0);
    CP_COMMIT();

    for (int kt = 0; kt <= ktmax; ++kt) {
        const int k0 = kt * 64;
        __syncthreads();
        if (kt + 1 <= ktmax) {
            FLASH_ISSUE(kt + 1, (kt + 1) & 1);
            CP_COMMIT();
            CP_WAIT1();
        } else {
            CP_WAIT0();
        }
        __syncthreads();

        const uint32_t stg = (uint32_t)(kt & 1) * KVTILE;
        const uint32_t kLane = kLane0 + stg;
        const uint32_t vLane = vLane0 + stg;

        // ---- S = q * k^T ----
        float sacc[8][4];
#pragma unroll
        for (int i = 0; i < 8; ++i)
#pragma unroll
            for (int j = 0; j < 4; ++j) sacc[i][j] = 0.f;

#pragma unroll
        for (int ks = 0; ks < 8; ++ks) {
            uint32_t ah[4];
            ldsm4(ah, qLane + ks * 32);
#pragma unroll
            for (int g = 0; g < 4; ++g) {
                uint32_t bhf[4];
                ldsm4(bhf, kLane + g * (16 * ASTR) + ks * 32);
                mma16816f(sacc[2 * g],     ah, bhf[0], bhf[1]);
                mma16816f(sacc[2 * g + 1], ah, bhf[2], bhf[3]);
            }
        }

        // ---- causal mask (only last two K tiles can cross the diagonal) ----
        if (k0 + 63 > q0) {
            const int rA = q0 + w * 16 + (lane >> 2);
#pragma unroll
            for (int nt = 0; nt < 8; ++nt) {
#pragma unroll
                for (int e = 0; e < 4; ++e) {
                    int col = k0 + nt * 8 + (lane & 3) * 2 + (e & 1);
                    int row = rA + ((e & 2) ? 8 : 0);
                    if (col > row) sacc[nt][e] = -CUDART_INF_F;
                }
            }
        }

        // ---- online softmax ----
        float mx0 = -CUDART_INF_F, mx1 = -CUDART_INF_F;
#pragma unroll
        for (int nt = 0; nt < 8; ++nt) {
            mx0 = fmaxf(mx0, fmaxf(sacc[nt][0], sacc[nt][1]));
            mx1 = fmaxf(mx1, fmaxf(sacc[nt][2], sacc[nt][3]));
        }
        mx0 = fmaxf(mx0, __shfl_xor_sync(0xffffffffu, mx0, 1));
        mx0 = fmaxf(mx0, __shfl_xor_sync(0xffffffffu, mx0, 2));
        mx1 = fmaxf(mx1, __shfl_xor_sync(0xffffffffu, mx1, 1));
        mx1 = fmaxf(mx1, __shfl_xor_sync(0xffffffffu, mx1, 2));
        float mn0 = fmaxf(mrow[0], mx0 * SCALE_LOG2E);
        float mn1 = fmaxf(mrow[1], mx1 * SCALE_LOG2E);
        float alpha0 = exp2f(mrow[0] - mn0);
        float alpha1 = exp2f(mrow[1] - mn1);
        mrow[0] = mn0; mrow[1] = mn1;

        float sum0 = 0.f, sum1 = 0.f;
#pragma unroll
        for (int nt = 0; nt < 8; ++nt) {
            float p0 = exp2f(sacc[nt][0] * SCALE_LOG2E - mn0);
            float p1 = exp2f(sacc[nt][1] * SCALE_LOG2E - mn0);
            float p2 = exp2f(sacc[nt][2] * SCALE_LOG2E - mn1);
            float p3 = exp2f(sacc[nt][3] * SCALE_LOG2E - mn1);
            sacc[nt][0] = p0; sacc[nt][1] = p1;
            sacc[nt][2] = p2; sacc[nt][3] = p3;
            sum0 += p0 + p1;
            sum1 += p2 + p3;
        }
        sum0 += __shfl_xor_sync(0xffffffffu, sum0, 1);
        sum0 += __shfl_xor_sync(0xffffffffu, sum0, 2);
        sum1 += __shfl_xor_sync(0xffffffffu, sum1, 1);
        sum1 += __shfl_xor_sync(0xffffffffu, sum1, 2);
        lrow[0] = alpha0 * lrow[0] + sum0;
        lrow[1] = alpha1 * lrow[1] + sum1;

#pragma unroll
        for (int nt = 0; nt < 16; ++nt) {
            o[nt][0] *= alpha0; o[nt][1] *= alpha0;
            o[nt][2] *= alpha1; o[nt][3] *= alpha1;
        }

        // ---- O += p * v ----
#pragma unroll
        for (int kc = 0; kc < 4; ++kc) {
            uint32_t pa_h[4];
#pragma unroll
            for (int half = 0; half < 2; ++half) {
                const float* s2 = sacc[2 * kc + half];
#pragma unroll
                for (int rr = 0; rr < 2; ++rr) {
                    pa_h[half * 2 + rr] = pack_f16x2(s2[rr * 2 + 0], s2[rr * 2 + 1]);
                }
            }
#pragma unroll
            for (int ng = 0; ng < 8; ++ng) {
                uint32_t vh[4];
                ldsm4t(vh, vLane + kc * (16 * ASTR) + ng * 32);
                mma16816f(o[2 * ng],     pa_h, vh[0], vh[1]);
                mma16816f(o[2 * ng + 1], pa_h, vh[2], vh[3]);
            }
        }
    }
#undef FLASH_ISSUE

    // ---- epilogue: normalize, write y hi ----
    const float inv0 = 1.0f / lrow[0];
    const float inv1 = 1.0f / lrow[1];
    const int rowA = q0 + w * 16 + (lane >> 2);
#pragma unroll
    for (int nt = 0; nt < 16; ++nt) {
        int col = h * DHEAD + nt * 8 + (lane & 3) * 2;
        uint32_t hp0 = pack_f16x2(o[nt][0] * inv0, o[nt][1] * inv0);
        uint32_t hp1 = pack_f16x2(o[nt][2] * inv1, o[nt][3] * inv1);
        size_t r0 = (size_t)(b * SEQ + rowA) * DMODEL + col;
        size_t r1 = (size_t)(b * SEQ + rowA + 8) * DMODEL + col;
        *reinterpret_cast<uint32_t*>(yh + r0) = hp0;
        *reinterpret_cast<uint32_t*>(yh + r1) = hp1;
    }
}

// ---------------------------------------------------------------------------
// Launch
// ---------------------------------------------------------------------------
extern "C" void kernel_launch(void* const* d_in, const int* in_sizes, int n_in,
                              void* d_out, int out_size)
{
    const float* x     = (const float*)d_in[0];
    const float* W_qkv = (const float*)d_in[1];
    const float* b_qkv = (const float*)d_in[2];
    const float* W_out = (const float*)d_in[3];
    const float* b_out = (const float*)d_in[4];
    float* out = (float*)d_out;

    void *p_xh, *p_wqh, *p_woh, *p_qh, *p_yh;
    cudaGetSymbolAddress(&p_xh, g_x_hi);
    cudaGetSymbolAddress(&p_wqh, g_wqkv_hi);
    cudaGetSymbolAddress(&p_woh, g_wout_hi);
    cudaGetSymbolAddress(&p_qh, g_qkv_hi);
    cudaGetSymbolAddress(&p_yh, g_y_hi);

    cudaFuncSetAttribute(gemm_mma_kernel,
                         cudaFuncAttributeMaxDynamicSharedMemorySize, GSMEM);
    cudaFuncSetAttribute(flash_mma_kernel,
                         cudaFuncAttributeMaxDynamicSharedMemorySize, FSMEM);

    // 0) Converts
    {
        int n4 = NTOK * DMODEL / 4;
        cvt_kernel<<<(n4 + 255) / 256, 256>>>(x, (__half*)p_xh, n4);
        dim3 blk(32, 8);
        transpose_cvt_kernel<<<dim3(QKVDIM / 32, DMODEL / 32), blk>>>(
            W_qkv, (__half*)p_wqh, DMODEL, QKVDIM);
        transpose_cvt_kernel<<<dim3(DMODEL / 32, DMODEL / 32), blk>>>(
            W_out, (__half*)p_woh, DMODEL, DMODEL);
    }

    // 1) QKV projection (pure fp16) -> qkv hi fp16
    gemm_mma_kernel<<<dim3(QKVDIM / TBN, NTOK / TBM), 256, GSMEM>>>(
        (const __half*)p_xh, (const __half*)p_wqh,
        b_qkv, nullptr, (__half*)p_qh,
        NTOK, QKVDIM, DMODEL);

    // 2) Attention (BM=128 flash, cp.async pipelined) -> y hi fp16
    flash_mma_kernel<<<dim3(SEQ / 128, BATCH * NHEADS), 256, FSMEM>>>(
        (const __half*)p_qh, (__half*)p_yh);

    // 3) Output projection (pure fp16) -> fp32 out
    gemm_mma_kernel<<<dim3(DMODEL / TBN, NTOK / TBM), 256, GSMEM>>>(
        (const __half*)p_yh, (const __half*)p_woh,
        b_out, out, nullptr,
        NTOK, DMODEL, DMODEL);
}

// round 17
// speedup vs baseline: 1.1999x; 1.0656x over previous
#include <cuda_runtime.h>
#include <cuda_fp16.h>
#include <math_constants.h>
#include <cstdint>

// Problem constants
#define BATCH   4
#define SEQ     2048
#define DMODEL  2048
#define NHEADS  16
#define DHEAD   128
#define QKVDIM  (3 * DMODEL)       // 6144
#define NTOK    (BATCH * SEQ)      // 8192

// ---------------------------------------------------------------------------
// Scratch (__device__ globals; no cudaMalloc allowed)
// ---------------------------------------------------------------------------
__device__ __half g_x_hi[(size_t)NTOK * DMODEL];
__device__ __half g_wqkv_hi[(size_t)QKVDIM * DMODEL];  // transposed [N,K]
__device__ __half g_wout_hi[(size_t)DMODEL * DMODEL];  // transposed [N,K]
__device__ __half g_qkv_hi[(size_t)NTOK * QKVDIM];
__device__ __half g_y_hi[(size_t)NTOK * DMODEL];

// ---------------------------------------------------------------------------
// Warp-MMA / async-copy helpers (plain PTX, compute_103-safe)
// ---------------------------------------------------------------------------
__device__ __forceinline__ uint32_t smem_u32(const void* p) {
    uint32_t a;
    asm("{ .reg .u64 t; cvta.to.shared.u64 t, %1; cvt.u32.u64 %0, t; }"
        : "=r"(a) : "l"(p));
    return a;
}

__device__ __forceinline__ void ldsm4(uint32_t r[4], uint32_t addr) {
    asm volatile("ldmatrix.sync.aligned.m8n8.x4.shared.b16 {%0,%1,%2,%3}, [%4];"
                 : "=r"(r[0]), "=r"(r[1]), "=r"(r[2]), "=r"(r[3]) : "r"(addr));
}
__device__ __forceinline__ void ldsm4t(uint32_t r[4], uint32_t addr) {
    asm volatile("ldmatrix.sync.aligned.m8n8.x4.trans.shared.b16 {%0,%1,%2,%3}, [%4];"
                 : "=r"(r[0]), "=r"(r[1]), "=r"(r[2]), "=r"(r[3]) : "r"(addr));
}

__device__ __forceinline__ void mma16816f(float c[4], const uint32_t a[4],
                                          uint32_t b0, uint32_t b1) {
    asm volatile(
        "mma.sync.aligned.m16n8k16.row.col.f32.f16.f16.f32 "
        "{%0,%1,%2,%3}, {%4,%5,%6,%7}, {%8,%9}, {%0,%1,%2,%3};"
        : "+f"(c[0]), "+f"(c[1]), "+f"(c[2]), "+f"(c[3])
        : "r"(a[0]), "r"(a[1]), "r"(a[2]), "r"(a[3]), "r"(b0), "r"(b1));
}

// pack two fp32 -> f16x2 (first arg in bits [0,16))
__device__ __forceinline__ uint32_t pack_f16x2(float lo, float hi) {
    uint32_t r;
    asm("cvt.rn.f16x2.f32 %0, %1, %2;" : "=r"(r) : "f"(hi), "f"(lo));
    return r;
}

__device__ __forceinline__ void cp16(uint32_t dst, const void* src) {
    asm volatile("cp.async.cg.shared.global [%0], [%1], 16;"
                 :: "r"(dst), "l"(src));
}
#define CP_COMMIT() asm volatile("cp.async.commit_group;" ::: "memory")
#define CP_WAIT0()  asm volatile("cp.async.wait_group 0;" ::: "memory")
#define CP_WAIT1()  asm volatile("cp.async.wait_group 1;" ::: "memory")

// ---------------------------------------------------------------------------
// Convert kernels
// ---------------------------------------------------------------------------
__global__ void cvt_kernel(const float* __restrict__ in,
                           __half* __restrict__ hi, int n4)
{
    int i = blockIdx.x * blockDim.x + threadIdx.x;
    if (i >= n4) return;
    float4 v = reinterpret_cast<const float4*>(in)[i];
    unsigned short hraw[4];
    hraw[0] = __half_as_ushort(__float2half_rn(v.x));
    hraw[1] = __half_as_ushort(__float2half_rn(v.y));
    hraw[2] = __half_as_ushort(__float2half_rn(v.z));
    hraw[3] = __half_as_ushort(__float2half_rn(v.w));
    reinterpret_cast<uint64_t*>(hi)[i] = *reinterpret_cast<uint64_t*>(hraw);
}

// W [K,N] fp32 -> Thi [N,K] fp16 (transpose + round; hi only)
__global__ void transpose_cvt_kernel(const float* __restrict__ W,
                                     __half* __restrict__ Thi,
                                     int K, int N)
{
    __shared__ float tile[32][33];
    int nx = blockIdx.x * 32 + threadIdx.x;
    int k0 = blockIdx.y * 32;
#pragma unroll
    for (int j = 0; j < 32; j += 8)
        tile[threadIdx.y + j][threadIdx.x] = W[(size_t)(k0 + threadIdx.y + j) * N + nx];
    __syncthreads();
    int k = k0 + threadIdx.x;
    int nbase = blockIdx.x * 32 + threadIdx.y;
#pragma unroll
    for (int j = 0; j < 32; j += 8)
        Thi[(size_t)(nbase + j) * K + k] = __float2half_rn(tile[threadIdx.x][threadIdx.y + j]);
}

// ---------------------------------------------------------------------------
// fp16 GEMM via warp mma.sync, 3-stage cp.async pipeline, 1 sync/chunk:
//   C[M,N] = A[M,K] @ B[N,K]^T + bias
// CTA tile 128x128, 8 warps (2 M x 4 N), warp tile 64x32, K-chunk 64, 2 CTA/SM.
// ---------------------------------------------------------------------------
#define TBM 128
#define TBN 128
#define TKC 64
#define STRB 144                 // smem row stride bytes (64 fp16 + 16 pad)
#define TILEB (128 * STRB)       // 18432
#define STAGEB (2 * TILEB)       // 36864: [A][B]
#define NSTAGE 3
#define GSMEM (NSTAGE * STAGEB)  // 110592

__global__ __launch_bounds__(256, 2)
void gemm_mma_kernel(const __half* __restrict__ Ahi,
                     const __half* __restrict__ Bhi,
                     const float* __restrict__ bias,
                     float* __restrict__ Cf,
                     __half* __restrict__ Chi,
                     int M, int N, int K)
{
    extern __shared__ char sm[];
    const uint32_t sbase = smem_u32(sm);
    const int tid = threadIdx.x;
    const int wid = tid >> 5;
    const int lane = tid & 31;
    const int m0 = blockIdx.y * TBM;
    const int n0 = blockIdx.x * TBN;
    const int wm = wid & 1;
    const int wn = wid >> 1;

    const int lc16 = tid & 7;

    float acc[4][4][4];
#pragma unroll
    for (int i = 0; i < 4; ++i)
#pragma unroll
        for (int j = 0; j < 4; ++j)
#pragma unroll
            for (int k = 0; k < 4; ++k) acc[i][j][k] = 0.f;

    const int arow = lane & 15;
    const int akb  = (lane & 16) ? 16 : 0;
    const int brow = ((lane & 16) ? 8 : 0) + (lane & 7);
    const int bkb  = (lane & 8) ? 16 : 0;

    const uint32_t aL = sbase + (wm * 64 + arow) * STRB + akb;
    const uint32_t bL = sbase + TILEB + (wn * 32 + brow) * STRB + bkb;

    const int nchunk = K / TKC;

#define GEMM_ISSUE(CHUNK, STAGE)                                              \
    {                                                                         \
        const int k0_ = (CHUNK) * TKC;                                        \
        const uint32_t sb_ = sbase + (STAGE) * STAGEB;                        \
        _Pragma("unroll")                                                     \
        for (int l = 0; l < 4; ++l) {                                         \
            int row = (tid + l * 256) >> 3;                                   \
            uint32_t so = row * STRB + lc16 * 16;                             \
            size_t ga = (size_t)(m0 + row) * K + k0_ + lc16 * 8;              \
            size_t gb = (size_t)(n0 + row) * K + k0_ + lc16 * 8;              \
            cp16(sb_ + so, Ahi + ga);                                         \
            cp16(sb_ + TILEB + so, Bhi + gb);                                 \
        }                                                                     \
    }

    // Prologue: fill stages 0 and 1
    GEMM_ISSUE(0, 0);
    CP_COMMIT();
    if (nchunk > 1) { GEMM_ISSUE(1, 1); CP_COMMIT(); }

    int stage = 0;
    for (int c = 0; c < nchunk; ++c) {
        if (c + 1 < nchunk) { CP_WAIT1(); } else { CP_WAIT0(); }
        __syncthreads();   // single barrier per chunk (3-stage safety)

        const uint32_t stoff = (uint32_t)stage * STAGEB;
#pragma unroll
        for (int ks = 0; ks < 4; ++ks) {
            uint32_t ah[4][4], bh[2][4];
#pragma unroll
            for (int mt = 0; mt < 4; ++mt)
                ldsm4(ah[mt], aL + stoff + mt * (16 * STRB) + ks * 32);
#pragma unroll
            for (int np = 0; np < 2; ++np)
                ldsm4(bh[np], bL + stoff + np * (16 * STRB) + ks * 32);
#pragma unroll
            for (int mt = 0; mt < 4; ++mt)
#pragma unroll
                for (int nt = 0; nt < 4; ++nt)
                    mma16816f(acc[mt][nt], ah[mt],
                              bh[nt >> 1][(nt & 1) * 2], bh[nt >> 1][(nt & 1) * 2 + 1]);
        }

        // Issue chunk c+2 into the stage read two iterations ago.
        if (c + 2 < nchunk) {
            int nstage = stage + 2; if (nstage >= NSTAGE) nstage -= NSTAGE;
            GEMM_ISSUE(c + 2, nstage);
            CP_COMMIT();
        }
        if (++stage == NSTAGE) stage = 0;
    }
#undef GEMM_ISSUE

    // Epilogue
    const int rbase = m0 + wm * 64 + (lane >> 2);
    const int cbase = n0 + wn * 32 + (lane & 3) * 2;
    if (Cf) {
#pragma unroll
        for (int mt = 0; mt < 4; ++mt) {
#pragma unroll
            for (int nt = 0; nt < 4; ++nt) {
                int r = rbase + mt * 16;
                int col = cbase + nt * 8;
                float2 bv = *reinterpret_cast<const float2*>(bias + col);
                float2 v0, v1;
                v0.x = acc[mt][nt][0] + bv.x;
                v0.y = acc[mt][nt][1] + bv.y;
                v1.x = acc[mt][nt][2] + bv.x;
                v1.y = acc[mt][nt][3] + bv.y;
                *reinterpret_cast<float2*>(Cf + (size_t)r * N + col) = v0;
                *reinterpret_cast<float2*>(Cf + (size_t)(r + 8) * N + col) = v1;
            }
        }
    } else {
#pragma unroll
        for (int mt = 0; mt < 4; ++mt) {
#pragma unroll
            for (int nt = 0; nt < 4; ++nt) {
                int r = rbase + mt * 16;
                int col = cbase + nt * 8;
                float2 bv = *reinterpret_cast<const float2*>(bias + col);
                uint32_t hp0 = pack_f16x2(acc[mt][nt][0] + bv.x,
                                          acc[mt][nt][1] + bv.y);
                uint32_t hp1 = pack_f16x2(acc[mt][nt][2] + bv.x,
                                          acc[mt][nt][3] + bv.y);
                *reinterpret_cast<uint32_t*>(Chi + (size_t)r * N + col) = hp0;
                *reinterpret_cast<uint32_t*>(Chi + (size_t)(r + 8) * N + col) = hp1;
            }
        }
    }
}

// ---------------------------------------------------------------------------
// Tensor-core flash attention (R13 config: BM=64, BN=64, D=128), causal,
// muP 1/DHEAD, cp.async double-buffered KV. 128 threads = 4 warps.
// ---------------------------------------------------------------------------
#define ASTR 272                 // smem row stride bytes (128 fp16 + 16 pad)
#define ATILE (64 * ASTR)        // 17408
#define FSM_Q  0
#define FSM_K0 (1 * ATILE)
#define FSM_K1 (2 * ATILE)
#define FSM_V0 (3 * ATILE)
#define FSM_V1 (4 * ATILE)
#define FSMEM  (5 * ATILE)       // 87040

__global__ __launch_bounds__(128, 2)
void flash_mma_kernel(const __half* __restrict__ qkvh,
                      __half* __restrict__ yh)
{
    extern __shared__ char sm[];
    const uint32_t sbase = smem_u32(sm);
    const int tid = threadIdx.x;
    const int w = tid >> 5;
    const int lane = tid & 31;

    const int qtile = blockIdx.x;
    const int bh = blockIdx.y;
    const int b = bh >> 4;
    const int h = bh & 15;
    const int q0 = qtile * 64;

#pragma unroll
    for (int l = 0; l < 8; ++l) {
        int f = tid + l * 128;
        int row = f >> 4;
        int c8 = f & 15;
        size_t g = (size_t)(b * SEQ + q0 + row) * QKVDIM + h * DHEAD + c8 * 8;
        uint32_t so = row * ASTR + c8 * 16;
        *reinterpret_cast<uint4*>(sm + FSM_Q + so) =
            *reinterpret_cast<const uint4*>(qkvh + g);
    }

    float o[16][4];
#pragma unroll
    for (int i = 0; i < 16; ++i)
#pragma unroll
        for (int j = 0; j < 4; ++j) o[i][j] = 0.f;
    float mrow[2] = {-CUDART_INF_F, -CUDART_INF_F};
    float lrow[2] = {0.f, 0.f};

    const uint32_t qLane = sbase + FSM_Q + (w * 16 + (lane & 15)) * ASTR +
                           ((lane & 16) ? 16 : 0);
    const uint32_t kLane0 = sbase + FSM_K0 +
                            (((lane & 16) ? 8 : 0) + (lane & 7)) * ASTR +
                            ((lane & 8) ? 16 : 0);
    const uint32_t vLane0 = sbase + FSM_V0 + (lane & 15) * ASTR +
                            ((lane & 16) ? 16 : 0);

    const float SCALE_LOG2E = (1.0f / (float)DHEAD) * 1.44269504088896f;

    const int kvc8 = tid & 15;

#define FLASH_ISSUE(KT, STAGE)                                                \
    {                                                                         \
        const int k0_ = (KT) * 64;                                            \
        const uint32_t koff = sbase + FSM_K0 + (STAGE) * ATILE;               \
        const uint32_t voff = sbase + FSM_V0 + (STAGE) * ATILE;               \
        _Pragma("unroll")                                                     \
        for (int l = 0; l < 8; ++l) {                                         \
            int row = (tid + l * 128) >> 4;                                   \
            size_t g = (size_t)(b * SEQ + k0_ + row) * QKVDIM +               \
                       h * DHEAD + kvc8 * 8;                                  \
            uint32_t so = row * ASTR + kvc8 * 16;                             \
            cp16(koff + so, qkvh + DMODEL + g);                               \
            cp16(voff + so, qkvh + 2 * DMODEL + g);                           \
        }                                                                     \
    }

    FLASH_ISSUE(0, 0);
    CP_COMMIT();

    for (int kt = 0; kt <= qtile; ++kt) {
        __syncthreads();
        if (kt + 1 <= qtile) {
            FLASH_ISSUE(kt + 1, (kt + 1) & 1);
            CP_COMMIT();
            CP_WAIT1();
        } else {
            CP_WAIT0();
        }
        __syncthreads();

        const uint32_t stg = (uint32_t)(kt & 1) * ATILE;
        const uint32_t kLane = kLane0 + stg;
        const uint32_t vLane = vLane0 + stg;

        float sacc[8][4];
#pragma unroll
        for (int i = 0; i < 8; ++i)
#pragma unroll
            for (int j = 0; j < 4; ++j) sacc[i][j] = 0.f;

#pragma unroll
        for (int ks = 0; ks < 8; ++ks) {
            uint32_t ah[4];
            ldsm4(ah, qLane + ks * 32);
#pragma unroll
            for (int g = 0; g < 4; ++g) {
                uint32_t bhf[4];
                ldsm4(bhf, kLane + g * (16 * ASTR) + ks * 32);
                mma16816f(sacc[2 * g],     ah, bhf[0], bhf[1]);
                mma16816f(sacc[2 * g + 1], ah, bhf[2], bhf[3]);
            }
        }

        if (kt == qtile) {
            const int rA = w * 16 + (lane >> 2);
#pragma unroll
            for (int nt = 0; nt < 8; ++nt) {
#pragma unroll
                for (int e = 0; e < 4; ++e) {
                    int col = nt * 8 + (lane & 3) * 2 + (e & 1);
                    int row = rA + ((e & 2) ? 8 : 0);
                    if (col > row) sacc[nt][e] = -CUDART_INF_F;
                }
            }
        }

        float mx0 = -CUDART_INF_F, mx1 = -CUDART_INF_F;
#pragma unroll
        for (int nt = 0; nt < 8; ++nt) {
            mx0 = fmaxf(mx0, fmaxf(sacc[nt][0], sacc[nt][1]));
            mx1 = fmaxf(mx1, fmaxf(sacc[nt][2], sacc[nt][3]));
        }
        mx0 = fmaxf(mx0, __shfl_xor_sync(0xffffffffu, mx0, 1));
        mx0 = fmaxf(mx0, __shfl_xor_sync(0xffffffffu, mx0, 2));
        mx1 = fmaxf(mx1, __shfl_xor_sync(0xffffffffu, mx1, 1));
        mx1 = fmaxf(mx1, __shfl_xor_sync(0xffffffffu, mx1, 2));
        float mn0 = fmaxf(mrow[0], mx0 * SCALE_LOG2E);
        float mn1 = fmaxf(mrow[1], mx1 * SCALE_LOG2E);
        float alpha0 = exp2f(mrow[0] - mn0);
        float alpha1 = exp2f(mrow[1] - mn1);
        mrow[0] = mn0; mrow[1] = mn1;

        float sum0 = 0.f, sum1 = 0.f;
#pragma unroll
        for (int nt = 0; nt < 8; ++nt) {
            float p0 = exp2f(sacc[nt][0] * SCALE_LOG2E - mn0);
            float p1 = exp2f(sacc[nt][1] * SCALE_LOG2E - mn0);
            float p2 = exp2f(sacc[nt][2] * SCALE_LOG2E - mn1);
            float p3 = exp2f(sacc[nt][3] * SCALE_LOG2E - mn1);
            sacc[nt][0] = p0; sacc[nt][1] = p1;
            sacc[nt][2] = p2; sacc[nt][3] = p3;
            sum0 += p0 + p1;
            sum1 += p2 + p3;
        }
        sum0 += __shfl_xor_sync(0xffffffffu, sum0, 1);
        sum0 += __shfl_xor_sync(0xffffffffu, sum0, 2);
        sum1 += __shfl_xor_sync(0xffffffffu, sum1, 1);
        sum1 += __shfl_xor_sync(0xffffffffu, sum1, 2);
        lrow[0] = alpha0 * lrow[0] + sum0;
        lrow[1] = alpha1 * lrow[1] + sum1;

#pragma unroll
        for (int nt = 0; nt < 16; ++nt) {
            o[nt][0] *= alpha0; o[nt][1] *= alpha0;
            o[nt][2] *= alpha1; o[nt][3] *= alpha1;
        }

#pragma unroll
        for (int kc = 0; kc < 4; ++kc) {
            uint32_t pa_h[4];
#pragma unroll
            for (int half = 0; half < 2; ++half) {
                const float* s2 = sacc[2 * kc + half];
#pragma unroll
                for (int rr = 0; rr < 2; ++rr) {
                    pa_h[half * 2 + rr] = pack_f16x2(s2[rr * 2 + 0], s2[rr * 2 + 1]);
                }
            }
#pragma unroll
            for (int ng = 0; ng < 8; ++ng) {
                uint32_t vh[4];
                ldsm4t(vh, vLane + kc * (16 * ASTR) + ng * 32);
                mma16816f(o[2 * ng],     pa_h, vh[0], vh[1]);
                mma16816f(o[2 * ng + 1], pa_h, vh[2], vh[3]);
            }
        }
    }
#undef FLASH_ISSUE

    const float inv0 = 1.0f / lrow[0];
    const float inv1 = 1.0f / lrow[1];
    const int rowA = q0 + w * 16 + (lane >> 2);
#pragma unroll
    for (int nt = 0; nt < 16; ++nt) {
        int col = h * DHEAD + nt * 8 + (lane & 3) * 2;
        uint32_t hp0 = pack_f16x2(o[nt][0] * inv0, o[nt][1] * inv0);
        uint32_t hp1 = pack_f16x2(o[nt][2] * inv1, o[nt][3] * inv1);
        size_t r0 = (size_t)(b * SEQ + rowA) * DMODEL + col;
        size_t r1 = (size_t)(b * SEQ + rowA + 8) * DMODEL + col;
        *reinterpret_cast<uint32_t*>(yh + r0) = hp0;
        *reinterpret_cast<uint32_t*>(yh + r1) = hp1;
    }
}

// ---------------------------------------------------------------------------
// Launch
// ---------------------------------------------------------------------------
extern "C" void kernel_launch(void* const* d_in, const int* in_sizes, int n_in,
                              void* d_out, int out_size)
{
    const float* x     = (const float*)d_in[0];
    const float* W_qkv = (const float*)d_in[1];
    const float* b_qkv = (const float*)d_in[2];
    const float* W_out = (const float*)d_in[3];
    const float* b_out = (const float*)d_in[4];
    float* out = (float*)d_out;

    void *p_xh, *p_wqh, *p_woh, *p_qh, *p_yh;
    cudaGetSymbolAddress(&p_xh, g_x_hi);
    cudaGetSymbolAddress(&p_wqh, g_wqkv_hi);
    cudaGetSymbolAddress(&p_woh, g_wout_hi);
    cudaGetSymbolAddress(&p_qh, g_qkv_hi);
    cudaGetSymbolAddress(&p_yh, g_y_hi);

    cudaFuncSetAttribute(gemm_mma_kernel,
                         cudaFuncAttributeMaxDynamicSharedMemorySize, GSMEM);
    cudaFuncSetAttribute(flash_mma_kernel,
                         cudaFuncAttributeMaxDynamicSharedMemorySize, FSMEM);

    // 0) Converts
    {
        int n4 = NTOK * DMODEL / 4;
        cvt_kernel<<<(n4 + 255) / 256, 256>>>(x, (__half*)p_xh, n4);
        dim3 blk(32, 8);
        transpose_cvt_kernel<<<dim3(QKVDIM / 32, DMODEL / 32), blk>>>(
            W_qkv, (__half*)p_wqh, DMODEL, QKVDIM);
        transpose_cvt_kernel<<<dim3(DMODEL / 32, DMODEL / 32), blk>>>(
            W_out, (__half*)p_woh, DMODEL, DMODEL);
    }

    // 1) QKV projection (pure fp16) -> qkv hi fp16
    gemm_mma_kernel<<<dim3(QKVDIM / TBN, NTOK / TBM), 256, GSMEM>>>(
        (const __half*)p_xh, (const __half*)p_wqh,
        b_qkv, nullptr, (__half*)p_qh,
        NTOK, QKVDIM, DMODEL);

    // 2) Attention (BM=64 flash, cp.async pipelined) -> y hi fp16
    flash_mma_kernel<<<dim3(SEQ / 64, BATCH * NHEADS), 128, FSMEM>>>(
        (const __half*)p_qh, (__half*)p_yh);

    // 3) Output projection (pure fp16) -> fp32 out
    gemm_mma_kernel<<<dim3(DMODEL / TBN, NTOK / TBM), 256, GSMEM>>>(
        (const __half*)p_yh, (const __half*)p_woh,
        b_out, out, nullptr,
        NTOK, DMODEL, DMODEL);
}